// round 1
// baseline (speedup 1.0000x reference)
#include <cuda_runtime.h>
#include <math.h>

// ContrastiveLoss: BS=8, C=64, N=4000
//   feat[b,n,c] = features[b,c,n,0]; rows L2-normalized
//   sim = featn @ featn^T / 0.1
//   pos: normal x normal, off-diag: mean(exp(sim)) -> -log(mean+eps)
//   neg: normal x anomaly: mean(-log(1-sigmoid(sim)+eps))
//   batch valid if n_norm>=10 && n_anom>=5; output = mean over valid batches.
//
// Strategy: compact rows (normal first) so we only compute the nn x N
// rectangle (~half the matrix). featn stored c-major [b][c][pos] so the
// fused GEMM loads tiles with coalesced float4 and conflict-free smem.

#define BSZ   8
#define CH    64
#define NN    4000
#define EPSC  1e-6f

__device__ float  g_featn[BSZ * CH * NN];   // [b][c][pos], 8 MB scratch
__device__ int    g_nn[BSZ];
__device__ double g_pos[BSZ];
__device__ double g_neg[BSZ];

// ---------------------------------------------------------------------------
// Kernel 1: per batch -> count normal, assign compacted positions (normal
// rows first), normalize each feature row, write c-major to g_featn.
// ---------------------------------------------------------------------------
__global__ void prep_kernel(const float* __restrict__ features,
                            const float* __restrict__ prob)
{
    const int b = blockIdx.x;
    const int t = threadIdx.x;
    const int T = 512;

    __shared__ int s_warp[T / 32];
    __shared__ int s_ctrN;
    __shared__ int s_ctrA;
    __shared__ int s_nn;

    // --- pass 1: count normal rows ---
    int cnt = 0;
    for (int n = t; n < NN; n += T)
        cnt += (prob[b * NN + n] < 0.5f) ? 1 : 0;
    #pragma unroll
    for (int o = 16; o; o >>= 1)
        cnt += __shfl_down_sync(0xffffffffu, cnt, o);
    if ((t & 31) == 0) s_warp[t >> 5] = cnt;
    __syncthreads();
    if (t == 0) {
        int nn = 0;
        #pragma unroll
        for (int w = 0; w < T / 32; w++) nn += s_warp[w];
        s_nn    = nn;
        g_nn[b] = nn;
        g_pos[b] = 0.0;
        g_neg[b] = 0.0;
        s_ctrN = 0;
        s_ctrA = nn;
    }
    __syncthreads();

    // --- pass 2: assign position, normalize, scatter c-major ---
    const float* fbase = features + (size_t)b * CH * NN;
    float*       obase = g_featn  + (size_t)b * CH * NN;
    for (int n = t; n < NN; n += T) {
        const bool isn = prob[b * NN + n] < 0.5f;
        const int pos = isn ? atomicAdd(&s_ctrN, 1) : atomicAdd(&s_ctrA, 1);

        float ss = 0.0f;
        #pragma unroll
        for (int c = 0; c < CH; c++) {
            float v = fbase[c * NN + n];
            ss = fmaf(v, v, ss);
        }
        const float inv = 1.0f / fmaxf(sqrtf(ss), 1e-12f);
        #pragma unroll
        for (int c = 0; c < CH; c++)
            obase[c * NN + pos] = fbase[c * NN + n] * inv;
    }
}

// ---------------------------------------------------------------------------
// Kernel 2: fused 128x128x64 fp32 GEMM + masked transcendental epilogue.
// Tile (i0, j0, b): rows i in [i0,i0+128) (must be < nn to matter),
// cols j in [j0,j0+128). K=64 split in 2 stages of 32 (smem = 2*16KB).
// ---------------------------------------------------------------------------
#define TI 128
#define TJ 128

__global__ __launch_bounds__(256, 2)
void sim_kernel()
{
    const int b  = blockIdx.z;
    const int i0 = blockIdx.y * TI;
    const int j0 = blockIdx.x * TJ;
    const int nn = g_nn[b];
    if (i0 >= nn) return;          // row-tile entirely outside normal set

    __shared__ float As[32][TI];   // [k][i]  16 KB
    __shared__ float Bs[32][TJ];   // [k][j]  16 KB

    const int t  = threadIdx.x;
    const int tx = t & 15;         // j micro-tile
    const int ty = t >> 4;         // i micro-tile

    const float* base = g_featn + (size_t)b * CH * NN;

    float acc[64];
    #pragma unroll
    for (int x = 0; x < 64; x++) acc[x] = 0.0f;

    #pragma unroll
    for (int stage = 0; stage < 2; stage++) {
        // --- load 32 k-rows of A and B tiles, coalesced float4 ---
        #pragma unroll
        for (int it = 0; it < 4; it++) {
            const int idx = it * 256 + t;     // 0..1023
            const int c   = idx >> 5;         // 0..31 (k within stage)
            const int col = (idx & 31) * 4;   // 0..124
            const float* rowp = base + (size_t)(stage * 32 + c) * NN;
            float4 av = make_float4(0.f, 0.f, 0.f, 0.f);
            float4 bv = av;
            if (i0 + col < NN) av = *(const float4*)(rowp + i0 + col);
            if (j0 + col < NN) bv = *(const float4*)(rowp + j0 + col);
            *(float4*)&As[c][col] = av;
            *(float4*)&Bs[c][col] = bv;
        }
        __syncthreads();

        // --- 32 k-steps, 8x8 register micro-tile per thread ---
        #pragma unroll 8
        for (int k = 0; k < 32; k++) {
            const float4 a0 = *(const float4*)&As[k][ty * 8];
            const float4 a1 = *(const float4*)&As[k][ty * 8 + 4];
            const float4 b0 = *(const float4*)&Bs[k][tx * 8];
            const float4 b1 = *(const float4*)&Bs[k][tx * 8 + 4];
            const float ar[8] = {a0.x, a0.y, a0.z, a0.w, a1.x, a1.y, a1.z, a1.w};
            const float br[8] = {b0.x, b0.y, b0.z, b0.w, b1.x, b1.y, b1.z, b1.w};
            #pragma unroll
            for (int ii = 0; ii < 8; ii++)
                #pragma unroll
                for (int jj = 0; jj < 8; jj++)
                    acc[ii * 8 + jj] = fmaf(ar[ii], br[jj], acc[ii * 8 + jj]);
        }
        __syncthreads();
    }

    // --- epilogue: masks + transcendentals, accumulate pos/neg ---
    float posS = 0.0f, negS = 0.0f;
    #pragma unroll
    for (int ii = 0; ii < 8; ii++) {
        const int i = i0 + ty * 8 + ii;
        const bool irow = (i < nn);
        #pragma unroll
        for (int jj = 0; jj < 8; jj++) {
            const int j = j0 + tx * 8 + jj;
            if (irow && j < NN) {
                const float s = acc[ii * 8 + jj] * 10.0f;   // /TEMPERATURE
                if (j < nn) {
                    if (i != j) posS += __expf(s);
                } else {
                    // -log(1 - sigmoid(s) + eps) = log(u) - log1p(eps*u), u = 1+e^s
                    const float e = __expf(s);
                    const float u = 1.0f + e;
                    const float x = EPSC * u;               // <= 0.023
                    negS += __logf(u) - x + 0.5f * x * x;
                }
            }
        }
    }

    // warp reduce, then one double atomic per warp
    #pragma unroll
    for (int o = 16; o; o >>= 1) {
        posS += __shfl_down_sync(0xffffffffu, posS, o);
        negS += __shfl_down_sync(0xffffffffu, negS, o);
    }
    if ((t & 31) == 0) {
        atomicAdd(&g_pos[b], (double)posS);
        atomicAdd(&g_neg[b], (double)negS);
    }
}

// ---------------------------------------------------------------------------
// Kernel 3: finalize -> scalar
// ---------------------------------------------------------------------------
__global__ void final_kernel(float* __restrict__ out)
{
    __shared__ float s_pb[BSZ];
    __shared__ int   s_v[BSZ];
    const int t = threadIdx.x;
    if (t < BSZ) {
        const int nn = g_nn[t];
        const int na = NN - nn;
        const bool valid = (nn >= 10) && (na >= 5);
        const float pos_cnt   = (float)nn * (float)(nn - 1);  // exact in fp32 (<2^24)
        const float cross_cnt = (float)nn * (float)na;
        const float pos_mean = (float)g_pos[t] / fmaxf(pos_cnt, 1.0f);
        const float pl = -__logf(pos_mean + EPSC);
        const float nl = (float)g_neg[t] / fmaxf(cross_cnt, 1.0f);
        s_pb[t] = valid ? (pl + nl) : 0.0f;
        s_v[t]  = valid ? 1 : 0;
    }
    __syncthreads();
    if (t == 0) {
        float sum = 0.0f;
        int v = 0;
        #pragma unroll
        for (int i = 0; i < BSZ; i++) { sum += s_pb[i]; v += s_v[i]; }
        out[0] = sum / fmaxf((float)v, 1.0f);
    }
}

// ---------------------------------------------------------------------------
extern "C" void kernel_launch(void* const* d_in, const int* in_sizes, int n_in,
                              void* d_out, int out_size)
{
    (void)in_sizes; (void)n_in; (void)out_size;
    const float* features = (const float*)d_in[0];   // (8,64,4000,1)
    const float* prob     = (const float*)d_in[1];   // (8,1,4000,1)
    float* out = (float*)d_out;

    prep_kernel<<<BSZ, 512>>>(features, prob);

    dim3 grid((NN + TJ - 1) / TJ, (NN + TI - 1) / TI, BSZ);
    sim_kernel<<<grid, 256>>>();

    final_kernel<<<1, 32>>>(out);
}

// round 2
// speedup vs baseline: 1.1962x; 1.1962x over previous
#include <cuda_runtime.h>
#include <math.h>

// ContrastiveLoss: BS=8, C=64, N=4000
// R2: (1) prep split into scan + wide scatter (8 -> 136 blocks),
//     (2) sim inner loop rewritten with packed fma.rn.f32x2 (FFMA2) to beat
//         the FFMA-3reg rt_SMSP=2 ceiling.

#define BSZ   8
#define CH    64
#define NN    4000
#define EPSC  1e-6f

__device__ float  g_featn[BSZ * CH * NN];   // [b][c][pos], 8 MB scratch
__device__ int    g_posidx[BSZ * NN];       // compacted position per row
__device__ int    g_nn[BSZ];
__device__ double g_pos[BSZ];
__device__ double g_neg[BSZ];

// ---------------------------------------------------------------------------
// P1: per batch, deterministic block scan -> compacted position for each row
// (normal rows first, order-preserving within each thread's stride walk).
// ---------------------------------------------------------------------------
__global__ void prep_index(const float* __restrict__ prob)
{
    const int b = blockIdx.x;
    const int t = threadIdx.x;          // 256 threads
    const int lane = t & 31;
    const int warp = t >> 5;

    // per-thread counts over strided rows
    int cntN = 0, cntA = 0;
    for (int n = t; n < NN; n += 256) {
        const bool isn = prob[b * NN + n] < 0.5f;
        cntN += isn ? 1 : 0;
        cntA += isn ? 0 : 1;
    }

    // inclusive warp scan
    int wN = cntN, wA = cntA;
    #pragma unroll
    for (int o = 1; o < 32; o <<= 1) {
        const int vN = __shfl_up_sync(0xffffffffu, wN, o);
        const int vA = __shfl_up_sync(0xffffffffu, wA, o);
        if (lane >= o) { wN += vN; wA += vA; }
    }

    __shared__ int sN[8], sA[8];
    __shared__ int s_nn;
    if (lane == 31) { sN[warp] = wN; sA[warp] = wA; }
    __syncthreads();

    int baseN = 0, baseA = 0;
    for (int w = 0; w < warp; w++) { baseN += sN[w]; baseA += sA[w]; }
    const int exclN = baseN + wN - cntN;
    const int exclA = baseA + wA - cntA;

    if (t == 255) {
        s_nn = baseN + wN;              // total normal count
        g_nn[b] = s_nn;
        g_pos[b] = 0.0;
        g_neg[b] = 0.0;
    }
    __syncthreads();
    const int nn = s_nn;

    int pN = exclN, pA = nn + exclA;
    for (int n = t; n < NN; n += 256) {
        const bool isn = prob[b * NN + n] < 0.5f;
        g_posidx[b * NN + n] = isn ? pN++ : pA++;
    }
}

// ---------------------------------------------------------------------------
// P2: normalize each row, scatter to c-major compacted layout. Wide grid.
// ---------------------------------------------------------------------------
__global__ __launch_bounds__(256)
void prep_scatter(const float* __restrict__ features)
{
    const int b = blockIdx.y;
    const int n = blockIdx.x * 256 + threadIdx.x;
    if (n >= NN) return;

    const int pos = g_posidx[b * NN + n];
    const float* fbase = features + (size_t)b * CH * NN;
    float*       obase = g_featn  + (size_t)b * CH * NN;

    float v[CH];
    float ss = 0.0f;
    #pragma unroll
    for (int c = 0; c < CH; c++) {
        v[c] = fbase[c * NN + n];
        ss = fmaf(v[c], v[c], ss);
    }
    const float inv = 1.0f / fmaxf(sqrtf(ss), 1e-12f);
    #pragma unroll
    for (int c = 0; c < CH; c++)
        obase[c * NN + pos] = v[c] * inv;
}

// ---------------------------------------------------------------------------
// Kernel 2: fused 128x128x64 fp32 GEMM (f32x2 packed FMA) + masked
// transcendental epilogue. Tile (i0, j0, b).
// ---------------------------------------------------------------------------
#define TI 128
#define TJ 128

#define FFMA2(acc, a, b) \
    asm("fma.rn.f32x2 %0, %1, %2, %0;" : "+l"(acc) : "l"(a), "l"(b))
#define PACK_DUP(d, s) \
    asm("mov.b64 %0, {%1, %1};" : "=l"(d) : "f"(s))
#define UNPACK2(lo, hi, v) \
    asm("mov.b64 {%0, %1}, %2;" : "=f"(lo), "=f"(hi) : "l"(v))

__global__ __launch_bounds__(256, 2)
void sim_kernel()
{
    const int b  = blockIdx.z;
    const int i0 = blockIdx.y * TI;
    const int j0 = blockIdx.x * TJ;
    const int nn = g_nn[b];
    if (i0 >= nn) return;          // row-tile entirely outside normal set

    __shared__ float As[32][TI];   // [k][i]  16 KB
    __shared__ float Bs[32][TJ];   // [k][j]  16 KB

    const int t  = threadIdx.x;
    const int tx = t & 15;         // j micro-tile (8 cols = 4 f32x2 pairs)
    const int ty = t >> 4;         // i micro-tile (8 rows)

    const float* base = g_featn + (size_t)b * CH * NN;

    // acc[ii*4+p] holds columns (2p, 2p+1) packed as f32x2
    unsigned long long acc[32];
    #pragma unroll
    for (int x = 0; x < 32; x++) acc[x] = 0ull;

    #pragma unroll
    for (int stage = 0; stage < 2; stage++) {
        // --- load 32 k-rows of A and B tiles, coalesced float4 ---
        #pragma unroll
        for (int it = 0; it < 4; it++) {
            const int idx = it * 256 + t;     // 0..1023
            const int c   = idx >> 5;         // 0..31 (k within stage)
            const int col = (idx & 31) * 4;   // 0..124
            const float* rowp = base + (size_t)(stage * 32 + c) * NN;
            float4 av = make_float4(0.f, 0.f, 0.f, 0.f);
            float4 bv = av;
            if (i0 + col < NN) av = *(const float4*)(rowp + i0 + col);
            if (j0 + col < NN) bv = *(const float4*)(rowp + j0 + col);
            *(float4*)&As[c][col] = av;
            *(float4*)&Bs[c][col] = bv;
        }
        __syncthreads();

        // --- 32 k-steps, 8x8 micro-tile as 8x(4 f32x2) per thread ---
        #pragma unroll 8
        for (int k = 0; k < 32; k++) {
            const ulonglong2 bq0 = *(const ulonglong2*)&Bs[k][tx * 8];
            const ulonglong2 bq1 = *(const ulonglong2*)&Bs[k][tx * 8 + 4];
            const unsigned long long bp[4] = {bq0.x, bq0.y, bq1.x, bq1.y};

            const float4 a0 = *(const float4*)&As[k][ty * 8];
            const float4 a1 = *(const float4*)&As[k][ty * 8 + 4];
            const float ar[8] = {a0.x, a0.y, a0.z, a0.w, a1.x, a1.y, a1.z, a1.w};

            #pragma unroll
            for (int ii = 0; ii < 8; ii++) {
                unsigned long long ad;
                PACK_DUP(ad, ar[ii]);
                #pragma unroll
                for (int p = 0; p < 4; p++)
                    FFMA2(acc[ii * 4 + p], ad, bp[p]);
            }
        }
        __syncthreads();
    }

    // --- epilogue: masks + transcendentals, accumulate pos/neg ---
    float posS = 0.0f, negS = 0.0f;
    #pragma unroll
    for (int ii = 0; ii < 8; ii++) {
        const int i = i0 + ty * 8 + ii;
        const bool irow = (i < nn);
        #pragma unroll
        for (int p = 0; p < 4; p++) {
            float v0, v1;
            UNPACK2(v0, v1, acc[ii * 4 + p]);
            #pragma unroll
            for (int h = 0; h < 2; h++) {
                const int j = j0 + tx * 8 + 2 * p + h;
                const float sv = (h == 0 ? v0 : v1) * 10.0f;  // /TEMPERATURE
                if (irow && j < NN) {
                    if (j < nn) {
                        if (i != j) posS += __expf(sv);
                    } else {
                        // -log(1-sigmoid(s)+eps) = log(u) - log1p(eps*u), u=1+e^s
                        const float e = __expf(sv);
                        const float u = 1.0f + e;
                        const float x = EPSC * u;             // <= 0.023
                        negS += __logf(u) - x + 0.5f * x * x;
                    }
                }
            }
        }
    }

    // warp reduce, then one double atomic per warp
    #pragma unroll
    for (int o = 16; o; o >>= 1) {
        posS += __shfl_down_sync(0xffffffffu, posS, o);
        negS += __shfl_down_sync(0xffffffffu, negS, o);
    }
    if ((t & 31) == 0) {
        atomicAdd(&g_pos[b], (double)posS);
        atomicAdd(&g_neg[b], (double)negS);
    }
}

// ---------------------------------------------------------------------------
// Kernel 3: finalize -> scalar
// ---------------------------------------------------------------------------
__global__ void final_kernel(float* __restrict__ out)
{
    __shared__ float s_pb[BSZ];
    __shared__ int   s_v[BSZ];
    const int t = threadIdx.x;
    if (t < BSZ) {
        const int nn = g_nn[t];
        const int na = NN - nn;
        const bool valid = (nn >= 10) && (na >= 5);
        const float pos_cnt   = (float)nn * (float)(nn - 1);  // exact in fp32
        const float cross_cnt = (float)nn * (float)na;
        const float pos_mean = (float)g_pos[t] / fmaxf(pos_cnt, 1.0f);
        const float pl = -__logf(pos_mean + EPSC);
        const float nl = (float)g_neg[t] / fmaxf(cross_cnt, 1.0f);
        s_pb[t] = valid ? (pl + nl) : 0.0f;
        s_v[t]  = valid ? 1 : 0;
    }
    __syncthreads();
    if (t == 0) {
        float sum = 0.0f;
        int v = 0;
        #pragma unroll
        for (int i = 0; i < BSZ; i++) { sum += s_pb[i]; v += s_v[i]; }
        out[0] = sum / fmaxf((float)v, 1.0f);
    }
}

// ---------------------------------------------------------------------------
extern "C" void kernel_launch(void* const* d_in, const int* in_sizes, int n_in,
                              void* d_out, int out_size)
{
    (void)in_sizes; (void)n_in; (void)out_size;
    const float* features = (const float*)d_in[0];   // (8,64,4000,1)
    const float* prob     = (const float*)d_in[1];   // (8,1,4000,1)
    float* out = (float*)d_out;

    prep_index<<<BSZ, 256>>>(prob);

    dim3 grid_sc((NN + 255) / 256, BSZ);
    prep_scatter<<<grid_sc, 256>>>(features);

    dim3 grid((NN + TJ - 1) / TJ, (NN + TI - 1) / TI, BSZ);
    sim_kernel<<<grid, 256>>>();

    final_kernel<<<1, 32>>>(out);
}

// round 4
// speedup vs baseline: 1.3086x; 1.0939x over previous
#include <cuda_runtime.h>
#include <cuda_bf16.h>
#include <math.h>
#include <stdint.h>

// ContrastiveLoss BS=8, C=64, N=4000 — R4: register-fragment bf16 HMMA
// (mma.sync m16n8k16, sm_100-compatible) with split-fp32 precision:
//   featn = hi + lo (bf16);  sim ~= Ahi@Bhi^T + Ahi@Blo^T + Alo@Bhi^T
// Rows compacted (normal first); pos quadrant via 2x lower-triangle symmetry.

#define BSZ   8
#define CH    64
#define NN    4000
#define NPAD  4096
#define EPSC  1e-6f
#define TI    128
#define TJ    128

__device__ __nv_bfloat16 g_hi[BSZ * NPAD * CH];  // [b][pos][c] K-major rows
__device__ __nv_bfloat16 g_lo[BSZ * NPAD * CH];
__device__ int    g_posidx[BSZ * NN];
__device__ int    g_nn[BSZ];
__device__ double g_pos[BSZ];
__device__ double g_neg[BSZ];

__device__ __forceinline__ uint32_t smem_u32(const void* p) {
    uint32_t a;
    asm("{ .reg .u64 t; cvta.to.shared.u64 t, %1; cvt.u32.u64 %0, t; }"
        : "=r"(a) : "l"(p));
    return a;
}

#define LDSM_X4(r0, r1, r2, r3, addr)                                          \
    asm volatile("ldmatrix.sync.aligned.m8n8.x4.shared.b16 {%0,%1,%2,%3}, [%4];"\
                 : "=r"(r0), "=r"(r1), "=r"(r2), "=r"(r3) : "r"(addr))

#define MMA16816(d, a, b0, b1)                                                 \
    asm volatile("mma.sync.aligned.m16n8k16.row.col.f32.bf16.bf16.f32 "        \
                 "{%0,%1,%2,%3}, {%4,%5,%6,%7}, {%8,%9}, {%0,%1,%2,%3};"       \
                 : "+f"((d)[0]), "+f"((d)[1]), "+f"((d)[2]), "+f"((d)[3])      \
                 : "r"((a)[0]), "r"((a)[1]), "r"((a)[2]), "r"((a)[3]),         \
                   "r"(b0), "r"(b1))

// ---------------------------------------------------------------------------
// P1: per batch deterministic scan -> compacted position per row.
// ---------------------------------------------------------------------------
__global__ void prep_index(const float* __restrict__ prob)
{
    const int b = blockIdx.x;
    const int t = threadIdx.x;          // 256 threads
    const int lane = t & 31;
    const int warp = t >> 5;

    int cntN = 0, cntA = 0;
    for (int n = t; n < NN; n += 256) {
        const bool isn = prob[b * NN + n] < 0.5f;
        cntN += isn ? 1 : 0;
        cntA += isn ? 0 : 1;
    }
    int wN = cntN, wA = cntA;
    #pragma unroll
    for (int o = 1; o < 32; o <<= 1) {
        const int vN = __shfl_up_sync(0xffffffffu, wN, o);
        const int vA = __shfl_up_sync(0xffffffffu, wA, o);
        if (lane >= o) { wN += vN; wA += vA; }
    }
    __shared__ int sN[8], sA[8];
    __shared__ int s_nn;
    if (lane == 31) { sN[warp] = wN; sA[warp] = wA; }
    __syncthreads();
    int baseN = 0, baseA = 0;
    for (int w = 0; w < warp; w++) { baseN += sN[w]; baseA += sA[w]; }
    const int exclN = baseN + wN - cntN;
    const int exclA = baseA + wA - cntA;
    if (t == 255) {
        s_nn = baseN + wN;
        g_nn[b] = s_nn;
        g_pos[b] = 0.0;
        g_neg[b] = 0.0;
    }
    __syncthreads();
    const int nn = s_nn;
    int pN = exclN, pA = nn + exclA;
    for (int n = t; n < NN; n += 256) {
        const bool isn = prob[b * NN + n] < 0.5f;
        g_posidx[b * NN + n] = isn ? pN++ : pA++;
    }
}

// ---------------------------------------------------------------------------
// P2: normalize row, split to bf16 hi + lo, scatter row-major compacted.
// Rows [NN, NPAD) zero-filled.
// ---------------------------------------------------------------------------
__global__ __launch_bounds__(256)
void prep_scatter(const float* __restrict__ features)
{
    const int b = blockIdx.y;
    const int n = blockIdx.x * 256 + threadIdx.x;
    if (n >= NPAD) return;

    if (n >= NN) {
        uint32_t* ohi = (uint32_t*)(g_hi + ((size_t)b * NPAD + n) * CH);
        uint32_t* olo = (uint32_t*)(g_lo + ((size_t)b * NPAD + n) * CH);
        #pragma unroll
        for (int c = 0; c < CH / 2; c++) { ohi[c] = 0u; olo[c] = 0u; }
        return;
    }

    const int pos = g_posidx[b * NN + n];
    const float* fb = features + (size_t)b * CH * NN;

    float v[CH];
    float ss = 0.0f;
    #pragma unroll
    for (int c = 0; c < CH; c++) {
        v[c] = fb[c * NN + n];
        ss = fmaf(v[c], v[c], ss);
    }
    const float inv = 1.0f / fmaxf(sqrtf(ss), 1e-12f);

    uint32_t* ohi = (uint32_t*)(g_hi + ((size_t)b * NPAD + pos) * CH);
    uint32_t* olo = (uint32_t*)(g_lo + ((size_t)b * NPAD + pos) * CH);
    #pragma unroll
    for (int c2 = 0; c2 < CH / 2; c2++) {
        const float x0 = v[2 * c2] * inv;
        const float x1 = v[2 * c2 + 1] * inv;
        const __nv_bfloat16 h0 = __float2bfloat16(x0);
        const __nv_bfloat16 h1 = __float2bfloat16(x1);
        const __nv_bfloat16 l0 = __float2bfloat16(x0 - __bfloat162float(h0));
        const __nv_bfloat16 l1 = __float2bfloat16(x1 - __bfloat162float(h1));
        ohi[c2] = ((uint32_t)__bfloat16_as_ushort(h1) << 16) | __bfloat16_as_ushort(h0);
        olo[c2] = ((uint32_t)__bfloat16_as_ushort(l1) << 16) | __bfloat16_as_ushort(l0);
    }
}

// ---------------------------------------------------------------------------
// sim: 128x128 tile per CTA, 8 warps (4x2), warp tile 32x64.
// 3 HMMA passes (hi*hi, hi*lo, lo*hi) accumulate in fp32 fragments.
// smem: 4 tiles of 128 rows x 64 bf16 (128B rows), 16B-chunk XOR swizzle.
// ---------------------------------------------------------------------------
#define SA_HI 0
#define SA_LO 16384
#define SB_HI 32768
#define SB_LO 49152
#define SMEM_TOTAL 65536

__global__ __launch_bounds__(256)
void sim_kernel()
{
    const int b  = blockIdx.z;
    const int i0 = blockIdx.y * TI;
    const int j0 = blockIdx.x * TJ;
    const int nn = g_nn[b];
    if (i0 >= nn) return;                          // no normal rows
    if (j0 >= i0 + TI && j0 + TJ <= nn) return;    // strictly-upper pos tile

    extern __shared__ char smem[];
    __shared__ float red[16];
    const uint32_t sb = smem_u32(smem);
    const int t = threadIdx.x;
    const int lane = t & 31, warp = t >> 5;

    // ---- load 4 tiles; thread handles 4 16B chunks per tile ----
    {
        const char* srcAhi = (const char*)(g_hi + ((size_t)b * NPAD + i0) * CH);
        const char* srcAlo = (const char*)(g_lo + ((size_t)b * NPAD + i0) * CH);
        const char* srcBhi = (const char*)(g_hi + ((size_t)b * NPAD + j0) * CH);
        const char* srcBlo = (const char*)(g_lo + ((size_t)b * NPAD + j0) * CH);
        #pragma unroll
        for (int it = 0; it < 4; it++) {
            const int idx = t + it * 256;              // 0..1023
            const int r = idx >> 3, c = idx & 7;
            const int go = r * 128 + c * 16;
            const int so = r * 128 + ((c ^ (r & 7)) << 4);
            *(uint4*)(smem + SA_HI + so) = *(const uint4*)(srcAhi + go);
            *(uint4*)(smem + SA_LO + so) = *(const uint4*)(srcAlo + go);
            *(uint4*)(smem + SB_HI + so) = *(const uint4*)(srcBhi + go);
            *(uint4*)(smem + SB_LO + so) = *(const uint4*)(srcBlo + go);
        }
    }
    __syncthreads();

    const int wi = (warp & 3) * 32;   // warp row base within tile
    const int wj = (warp >> 2) * 64;  // warp col base within tile

    float acc[2][8][4];
    #pragma unroll
    for (int mt = 0; mt < 2; mt++)
        #pragma unroll
        for (int nt = 0; nt < 8; nt++)
            #pragma unroll
            for (int r = 0; r < 4; r++) acc[mt][nt][r] = 0.0f;

    #pragma unroll
    for (int pass = 0; pass < 3; pass++) {
        const uint32_t Abase = sb + (pass == 2 ? SA_LO : SA_HI);
        const uint32_t Bbase = sb + (pass == 1 ? SB_LO : SB_HI);
        #pragma unroll
        for (int ks = 0; ks < 4; ks++) {
            const int c0 = ks * 2;

            uint32_t a[2][4];
            #pragma unroll
            for (int mt = 0; mt < 2; mt++) {
                const int row = wi + mt * 16 + (lane & 15);
                const int ch  = c0 + (lane >> 4);
                const uint32_t addr = Abase + row * 128 + ((ch ^ (row & 7)) << 4);
                LDSM_X4(a[mt][0], a[mt][1], a[mt][2], a[mt][3], addr);
            }

            uint32_t bf[4][4];   // pair p covers n-tiles 2p, 2p+1
            #pragma unroll
            for (int p = 0; p < 4; p++) {
                const int row = wj + p * 16 + ((lane >> 4) << 3) + (lane & 7);
                const int ch  = c0 + ((lane >> 3) & 1);
                const uint32_t addr = Bbase + row * 128 + ((ch ^ (row & 7)) << 4);
                LDSM_X4(bf[p][0], bf[p][1], bf[p][2], bf[p][3], addr);
            }

            #pragma unroll
            for (int mt = 0; mt < 2; mt++)
                #pragma unroll
                for (int nt = 0; nt < 8; nt++)
                    MMA16816(acc[mt][nt], a[mt],
                             bf[nt >> 1][(nt & 1) * 2],
                             bf[nt >> 1][(nt & 1) * 2 + 1]);
        }
    }

    // ---- epilogue directly on fragments ----
    float posS = 0.0f, negS = 0.0f;
    #pragma unroll
    for (int mt = 0; mt < 2; mt++) {
        #pragma unroll
        for (int nt = 0; nt < 8; nt++) {
            #pragma unroll
            for (int r = 0; r < 4; r++) {
                const int i = i0 + wi + mt * 16 + (lane >> 2) + ((r >> 1) << 3);
                const int j = j0 + wj + nt * 8 + ((lane & 3) << 1) + (r & 1);
                const float s = acc[mt][nt][r] * 10.0f;   // /TEMPERATURE
                if (i < nn && j < NN) {
                    if (j < nn) {
                        if (j < i) posS += 2.0f * __expf(s);   // symmetry
                    } else {
                        // -log(1-sigmoid(s)+eps) = log(u) - log1p(eps*u), u=1+e^s
                        const float e = __expf(s);
                        const float u = 1.0f + e;
                        const float x = EPSC * u;              // <= 0.023
                        negS += __logf(u) - x + 0.5f * x * x;
                    }
                }
            }
        }
    }

    #pragma unroll
    for (int o = 16; o; o >>= 1) {
        posS += __shfl_down_sync(0xffffffffu, posS, o);
        negS += __shfl_down_sync(0xffffffffu, negS, o);
    }
    if (lane == 0) { red[warp] = posS; red[8 + warp] = negS; }
    __syncthreads();
    if (t == 0) {
        float p = 0.0f, q = 0.0f;
        #pragma unroll
        for (int w = 0; w < 8; w++) { p += red[w]; q += red[8 + w]; }
        if (p != 0.0f) atomicAdd(&g_pos[b], (double)p);
        if (q != 0.0f) atomicAdd(&g_neg[b], (double)q);
    }
}

// ---------------------------------------------------------------------------
__global__ void final_kernel(float* __restrict__ out)
{
    __shared__ float s_pb[BSZ];
    __shared__ int   s_v[BSZ];
    const int t = threadIdx.x;
    if (t < BSZ) {
        const int nn = g_nn[t];
        const int na = NN - nn;
        const bool valid = (nn >= 10) && (na >= 5);
        const float pos_cnt   = (float)nn * (float)(nn - 1);
        const float cross_cnt = (float)nn * (float)na;
        const float pos_mean = (float)g_pos[t] / fmaxf(pos_cnt, 1.0f);
        const float pl = -__logf(pos_mean + EPSC);
        const float nl = (float)g_neg[t] / fmaxf(cross_cnt, 1.0f);
        s_pb[t] = valid ? (pl + nl) : 0.0f;
        s_v[t]  = valid ? 1 : 0;
    }
    __syncthreads();
    if (t == 0) {
        float sum = 0.0f;
        int v = 0;
        #pragma unroll
        for (int i = 0; i < BSZ; i++) { sum += s_pb[i]; v += s_v[i]; }
        out[0] = sum / fmaxf((float)v, 1.0f);
    }
}

// ---------------------------------------------------------------------------
extern "C" void kernel_launch(void* const* d_in, const int* in_sizes, int n_in,
                              void* d_out, int out_size)
{
    (void)in_sizes; (void)n_in; (void)out_size;
    const float* features = (const float*)d_in[0];   // (8,64,4000,1)
    const float* prob     = (const float*)d_in[1];   // (8,1,4000,1)
    float* out = (float*)d_out;

    cudaFuncSetAttribute(sim_kernel,
                         cudaFuncAttributeMaxDynamicSharedMemorySize, SMEM_TOTAL);

    prep_index<<<BSZ, 256>>>(prob);

    dim3 grid_sc((NPAD + 255) / 256, BSZ);
    prep_scatter<<<grid_sc, 256>>>(features);

    dim3 grid(NPAD / TJ, NPAD / TI, BSZ);
    sim_kernel<<<grid, 256, SMEM_TOTAL>>>();

    final_kernel<<<1, 32>>>(out);
}

// round 5
// speedup vs baseline: 1.7273x; 1.3200x over previous
#include <cuda_runtime.h>
#include <cuda_fp16.h>
#include <math.h>
#include <stdint.h>

// ContrastiveLoss BS=8, C=64, N=4000 — R5:
//   fp16 split (hi + lo, 11+11 mantissa bits) register-fragment HMMA.
//   sim_pos (j0 < nn): 3 passes (hi*hi + hi*lo + lo*hi), pos + straddle-neg.
//   sim_neg (j0 >= nn): 1 pass hi*hi only (softplus tolerates 1e-3 s-error).
// Rows compacted (normal first); pos quadrant via 2x lower-triangle symmetry.

#define BSZ   8
#define CH    64
#define NN    4000
#define NPAD  4096
#define EPSC  1e-6f
#define TI    128
#define TJ    128

__device__ __half g_hi[BSZ * NPAD * CH];  // [b][pos][c] K-major rows
__device__ __half g_lo[BSZ * NPAD * CH];
__device__ int    g_posidx[BSZ * NN];
__device__ int    g_nn[BSZ];
__device__ double g_pos[BSZ];
__device__ double g_neg[BSZ];

__device__ __forceinline__ uint32_t smem_u32(const void* p) {
    uint32_t a;
    asm("{ .reg .u64 t; cvta.to.shared.u64 t, %1; cvt.u32.u64 %0, t; }"
        : "=r"(a) : "l"(p));
    return a;
}

#define LDSM_X4(r0, r1, r2, r3, addr)                                          \
    asm volatile("ldmatrix.sync.aligned.m8n8.x4.shared.b16 {%0,%1,%2,%3}, [%4];"\
                 : "=r"(r0), "=r"(r1), "=r"(r2), "=r"(r3) : "r"(addr))

#define MMA16816(d, a, b0, b1)                                                 \
    asm volatile("mma.sync.aligned.m16n8k16.row.col.f32.f16.f16.f32 "          \
                 "{%0,%1,%2,%3}, {%4,%5,%6,%7}, {%8,%9}, {%0,%1,%2,%3};"       \
                 : "+f"((d)[0]), "+f"((d)[1]), "+f"((d)[2]), "+f"((d)[3])      \
                 : "r"((a)[0]), "r"((a)[1]), "r"((a)[2]), "r"((a)[3]),         \
                   "r"(b0), "r"(b1))

// ---------------------------------------------------------------------------
// P1: per batch deterministic scan -> compacted position per row.
// ---------------------------------------------------------------------------
__global__ void prep_index(const float* __restrict__ prob)
{
    const int b = blockIdx.x;
    const int t = threadIdx.x;          // 256 threads
    const int lane = t & 31;
    const int warp = t >> 5;

    int cntN = 0, cntA = 0;
    for (int n = t; n < NN; n += 256) {
        const bool isn = prob[b * NN + n] < 0.5f;
        cntN += isn ? 1 : 0;
        cntA += isn ? 0 : 1;
    }
    int wN = cntN, wA = cntA;
    #pragma unroll
    for (int o = 1; o < 32; o <<= 1) {
        const int vN = __shfl_up_sync(0xffffffffu, wN, o);
        const int vA = __shfl_up_sync(0xffffffffu, wA, o);
        if (lane >= o) { wN += vN; wA += vA; }
    }
    __shared__ int sN[8], sA[8];
    __shared__ int s_nn;
    if (lane == 31) { sN[warp] = wN; sA[warp] = wA; }
    __syncthreads();
    int baseN = 0, baseA = 0;
    for (int w = 0; w < warp; w++) { baseN += sN[w]; baseA += sA[w]; }
    const int exclN = baseN + wN - cntN;
    const int exclA = baseA + wA - cntA;
    if (t == 255) {
        s_nn = baseN + wN;
        g_nn[b] = s_nn;
        g_pos[b] = 0.0;
        g_neg[b] = 0.0;
    }
    __syncthreads();
    const int nn = s_nn;
    int pN = exclN, pA = nn + exclA;
    for (int n = t; n < NN; n += 256) {
        const bool isn = prob[b * NN + n] < 0.5f;
        g_posidx[b * NN + n] = isn ? pN++ : pA++;
    }
}

// ---------------------------------------------------------------------------
// P2: normalize row, split to fp16 hi + lo, scatter row-major compacted.
// Rows [NN, NPAD) zero-filled.
// ---------------------------------------------------------------------------
__global__ __launch_bounds__(256)
void prep_scatter(const float* __restrict__ features)
{
    const int b = blockIdx.y;
    const int n = blockIdx.x * 256 + threadIdx.x;
    if (n >= NPAD) return;

    if (n >= NN) {
        uint32_t* ohi = (uint32_t*)(g_hi + ((size_t)b * NPAD + n) * CH);
        uint32_t* olo = (uint32_t*)(g_lo + ((size_t)b * NPAD + n) * CH);
        #pragma unroll
        for (int c = 0; c < CH / 2; c++) { ohi[c] = 0u; olo[c] = 0u; }
        return;
    }

    const int pos = g_posidx[b * NN + n];
    const float* fb = features + (size_t)b * CH * NN;

    float v[CH];
    float ss = 0.0f;
    #pragma unroll
    for (int c = 0; c < CH; c++) {
        v[c] = fb[c * NN + n];
        ss = fmaf(v[c], v[c], ss);
    }
    const float inv = 1.0f / fmaxf(sqrtf(ss), 1e-12f);

    uint32_t* ohi = (uint32_t*)(g_hi + ((size_t)b * NPAD + pos) * CH);
    uint32_t* olo = (uint32_t*)(g_lo + ((size_t)b * NPAD + pos) * CH);
    #pragma unroll
    for (int c2 = 0; c2 < CH / 2; c2++) {
        const float x0 = v[2 * c2] * inv;
        const float x1 = v[2 * c2 + 1] * inv;
        const __half h0 = __float2half_rn(x0);
        const __half h1 = __float2half_rn(x1);
        const __half l0 = __float2half_rn(x0 - __half2float(h0));
        const __half l1 = __float2half_rn(x1 - __half2float(h1));
        ohi[c2] = ((uint32_t)__half_as_ushort(h1) << 16) | __half_as_ushort(h0);
        olo[c2] = ((uint32_t)__half_as_ushort(l1) << 16) | __half_as_ushort(l0);
    }
}

// ---------------------------------------------------------------------------
// sim_pos: tiles with j0 < nn. 3 HMMA passes, full precision.
// 128x128 tile, 8 warps (4x2), warp tile 32x64.
// ---------------------------------------------------------------------------
#define SA_HI 0
#define SA_LO 16384
#define SB_HI 32768
#define SB_LO 49152
#define POS_SMEM 65536
#define NEG_SMEM 32768

__global__ __launch_bounds__(256)
void sim_pos_kernel()
{
    const int b  = blockIdx.z;
    const int i0 = blockIdx.y * TI;
    const int j0 = blockIdx.x * TJ;
    const int nn = g_nn[b];
    if (i0 >= nn || j0 >= nn) return;              // pos kernel: j0 < nn only
    if (j0 >= i0 + TI && j0 + TJ <= nn) return;    // strictly-upper all-pos tile

    extern __shared__ char smem[];
    __shared__ float red[16];
    const uint32_t sb = smem_u32(smem);
    const int t = threadIdx.x;
    const int lane = t & 31, warp = t >> 5;

    // ---- load 4 tiles; thread handles 4 16B chunks per tile ----
    {
        const char* srcAhi = (const char*)(g_hi + ((size_t)b * NPAD + i0) * CH);
        const char* srcAlo = (const char*)(g_lo + ((size_t)b * NPAD + i0) * CH);
        const char* srcBhi = (const char*)(g_hi + ((size_t)b * NPAD + j0) * CH);
        const char* srcBlo = (const char*)(g_lo + ((size_t)b * NPAD + j0) * CH);
        #pragma unroll
        for (int it = 0; it < 4; it++) {
            const int idx = t + it * 256;              // 0..1023
            const int r = idx >> 3, c = idx & 7;
            const int go = r * 128 + c * 16;
            const int so = r * 128 + ((c ^ (r & 7)) << 4);
            *(uint4*)(smem + SA_HI + so) = *(const uint4*)(srcAhi + go);
            *(uint4*)(smem + SA_LO + so) = *(const uint4*)(srcAlo + go);
            *(uint4*)(smem + SB_HI + so) = *(const uint4*)(srcBhi + go);
            *(uint4*)(smem + SB_LO + so) = *(const uint4*)(srcBlo + go);
        }
    }
    __syncthreads();

    const int wi = (warp & 3) * 32;
    const int wj = (warp >> 2) * 64;

    float acc[2][8][4];
    #pragma unroll
    for (int mt = 0; mt < 2; mt++)
        #pragma unroll
        for (int nt = 0; nt < 8; nt++)
            #pragma unroll
            for (int r = 0; r < 4; r++) acc[mt][nt][r] = 0.0f;

    #pragma unroll
    for (int pass = 0; pass < 3; pass++) {
        const uint32_t Abase = sb + (pass == 2 ? SA_LO : SA_HI);
        const uint32_t Bbase = sb + (pass == 1 ? SB_LO : SB_HI);
        #pragma unroll
        for (int ks = 0; ks < 4; ks++) {
            const int c0 = ks * 2;
            uint32_t a[2][4];
            #pragma unroll
            for (int mt = 0; mt < 2; mt++) {
                const int row = wi + mt * 16 + (lane & 15);
                const int ch  = c0 + (lane >> 4);
                LDSM_X4(a[mt][0], a[mt][1], a[mt][2], a[mt][3],
                        Abase + row * 128 + ((ch ^ (row & 7)) << 4));
            }
            uint32_t bf[4][4];
            #pragma unroll
            for (int p = 0; p < 4; p++) {
                const int row = wj + p * 16 + ((lane >> 4) << 3) + (lane & 7);
                const int ch  = c0 + ((lane >> 3) & 1);
                LDSM_X4(bf[p][0], bf[p][1], bf[p][2], bf[p][3],
                        Bbase + row * 128 + ((ch ^ (row & 7)) << 4));
            }
            #pragma unroll
            for (int mt = 0; mt < 2; mt++)
                #pragma unroll
                for (int nt = 0; nt < 8; nt++)
                    MMA16816(acc[mt][nt], a[mt],
                             bf[nt >> 1][(nt & 1) * 2],
                             bf[nt >> 1][(nt & 1) * 2 + 1]);
        }
    }

    // ---- epilogue on fragments: pos (2x lower tri) + straddle neg ----
    float posS = 0.0f, negS = 0.0f;
    #pragma unroll
    for (int mt = 0; mt < 2; mt++) {
        #pragma unroll
        for (int nt = 0; nt < 8; nt++) {
            #pragma unroll
            for (int r = 0; r < 4; r++) {
                const int i = i0 + wi + mt * 16 + (lane >> 2) + ((r >> 1) << 3);
                const int j = j0 + wj + nt * 8 + ((lane & 3) << 1) + (r & 1);
                const float s = acc[mt][nt][r] * 10.0f;
                if (i < nn && j < NN) {
                    if (j < nn) {
                        if (j < i) posS += 2.0f * __expf(s);
                    } else {
                        const float e = __expf(s);
                        const float u = 1.0f + e;
                        const float x = EPSC * u;
                        negS += __logf(u) - x + 0.5f * x * x;
                    }
                }
            }
        }
    }

    #pragma unroll
    for (int o = 16; o; o >>= 1) {
        posS += __shfl_down_sync(0xffffffffu, posS, o);
        negS += __shfl_down_sync(0xffffffffu, negS, o);
    }
    if (lane == 0) { red[warp] = posS; red[8 + warp] = negS; }
    __syncthreads();
    if (t == 0) {
        float p = 0.0f, q = 0.0f;
        #pragma unroll
        for (int w = 0; w < 8; w++) { p += red[w]; q += red[8 + w]; }
        if (p != 0.0f) atomicAdd(&g_pos[b], (double)p);
        if (q != 0.0f) atomicAdd(&g_neg[b], (double)q);
    }
}

// ---------------------------------------------------------------------------
// sim_neg: tiles with j0 >= nn (pure cross region). 1 HMMA pass, hi only.
// ---------------------------------------------------------------------------
__global__ __launch_bounds__(256)
void sim_neg_kernel()
{
    const int b  = blockIdx.z;
    const int i0 = blockIdx.y * TI;
    const int j0 = blockIdx.x * TJ;
    const int nn = g_nn[b];
    if (i0 >= nn || j0 < nn || j0 >= NN) return;   // straddle handled by pos

    extern __shared__ char smem[];
    __shared__ float red[8];
    const uint32_t sb = smem_u32(smem);
    const int t = threadIdx.x;
    const int lane = t & 31, warp = t >> 5;

    // ---- load 2 tiles (A_hi, B_hi) ----
    {
        const char* srcAhi = (const char*)(g_hi + ((size_t)b * NPAD + i0) * CH);
        const char* srcBhi = (const char*)(g_hi + ((size_t)b * NPAD + j0) * CH);
        #pragma unroll
        for (int it = 0; it < 4; it++) {
            const int idx = t + it * 256;
            const int r = idx >> 3, c = idx & 7;
            const int go = r * 128 + c * 16;
            const int so = r * 128 + ((c ^ (r & 7)) << 4);
            *(uint4*)(smem + 0     + so) = *(const uint4*)(srcAhi + go);
            *(uint4*)(smem + 16384 + so) = *(const uint4*)(srcBhi + go);
        }
    }
    __syncthreads();

    const int wi = (warp & 3) * 32;
    const int wj = (warp >> 2) * 64;

    float acc[2][8][4];
    #pragma unroll
    for (int mt = 0; mt < 2; mt++)
        #pragma unroll
        for (int nt = 0; nt < 8; nt++)
            #pragma unroll
            for (int r = 0; r < 4; r++) acc[mt][nt][r] = 0.0f;

    #pragma unroll
    for (int ks = 0; ks < 4; ks++) {
        const int c0 = ks * 2;
        uint32_t a[2][4];
        #pragma unroll
        for (int mt = 0; mt < 2; mt++) {
            const int row = wi + mt * 16 + (lane & 15);
            const int ch  = c0 + (lane >> 4);
            LDSM_X4(a[mt][0], a[mt][1], a[mt][2], a[mt][3],
                    sb + row * 128 + ((ch ^ (row & 7)) << 4));
        }
        uint32_t bf[4][4];
        #pragma unroll
        for (int p = 0; p < 4; p++) {
            const int row = wj + p * 16 + ((lane >> 4) << 3) + (lane & 7);
            const int ch  = c0 + ((lane >> 3) & 1);
            LDSM_X4(bf[p][0], bf[p][1], bf[p][2], bf[p][3],
                    sb + 16384 + row * 128 + ((ch ^ (row & 7)) << 4));
        }
        #pragma unroll
        for (int mt = 0; mt < 2; mt++)
            #pragma unroll
            for (int nt = 0; nt < 8; nt++)
                MMA16816(acc[mt][nt], a[mt],
                         bf[nt >> 1][(nt & 1) * 2],
                         bf[nt >> 1][(nt & 1) * 2 + 1]);
    }

    // ---- epilogue: neg only (all j >= nn here) ----
    float negS = 0.0f;
    #pragma unroll
    for (int mt = 0; mt < 2; mt++) {
        #pragma unroll
        for (int nt = 0; nt < 8; nt++) {
            #pragma unroll
            for (int r = 0; r < 4; r++) {
                const int i = i0 + wi + mt * 16 + (lane >> 2) + ((r >> 1) << 3);
                const int j = j0 + wj + nt * 8 + ((lane & 3) << 1) + (r & 1);
                if (i < nn && j < NN) {
                    const float s = acc[mt][nt][r] * 10.0f;
                    const float e = __expf(s);
                    const float u = 1.0f + e;
                    const float x = EPSC * u;
                    negS += __logf(u) - x + 0.5f * x * x;
                }
            }
        }
    }

    #pragma unroll
    for (int o = 16; o; o >>= 1)
        negS += __shfl_down_sync(0xffffffffu, negS, o);
    if (lane == 0) red[warp] = negS;
    __syncthreads();
    if (t == 0) {
        float q = 0.0f;
        #pragma unroll
        for (int w = 0; w < 8; w++) q += red[w];
        if (q != 0.0f) atomicAdd(&g_neg[b], (double)q);
    }
}

// ---------------------------------------------------------------------------
__global__ void final_kernel(float* __restrict__ out)
{
    __shared__ float s_pb[BSZ];
    __shared__ int   s_v[BSZ];
    const int t = threadIdx.x;
    if (t < BSZ) {
        const int nn = g_nn[t];
        const int na = NN - nn;
        const bool valid = (nn >= 10) && (na >= 5);
        const float pos_cnt   = (float)nn * (float)(nn - 1);
        const float cross_cnt = (float)nn * (float)na;
        const float pos_mean = (float)g_pos[t] / fmaxf(pos_cnt, 1.0f);
        const float pl = -__logf(pos_mean + EPSC);
        const float nl = (float)g_neg[t] / fmaxf(cross_cnt, 1.0f);
        s_pb[t] = valid ? (pl + nl) : 0.0f;
        s_v[t]  = valid ? 1 : 0;
    }
    __syncthreads();
    if (t == 0) {
        float sum = 0.0f;
        int v = 0;
        #pragma unroll
        for (int i = 0; i < BSZ; i++) { sum += s_pb[i]; v += s_v[i]; }
        out[0] = sum / fmaxf((float)v, 1.0f);
    }
}

// ---------------------------------------------------------------------------
extern "C" void kernel_launch(void* const* d_in, const int* in_sizes, int n_in,
                              void* d_out, int out_size)
{
    (void)in_sizes; (void)n_in; (void)out_size;
    const float* features = (const float*)d_in[0];   // (8,64,4000,1)
    const float* prob     = (const float*)d_in[1];   // (8,1,4000,1)
    float* out = (float*)d_out;

    cudaFuncSetAttribute(sim_pos_kernel,
                         cudaFuncAttributeMaxDynamicSharedMemorySize, POS_SMEM);
    cudaFuncSetAttribute(sim_neg_kernel,
                         cudaFuncAttributeMaxDynamicSharedMemorySize, NEG_SMEM);

    prep_index<<<BSZ, 256>>>(prob);

    dim3 grid_sc((NPAD + 255) / 256, BSZ);
    prep_scatter<<<grid_sc, 256>>>(features);

    dim3 grid(NPAD / TJ, NPAD / TI, BSZ);
    sim_pos_kernel<<<grid, 256, POS_SMEM>>>();
    sim_neg_kernel<<<grid, 256, NEG_SMEM>>>();

    final_kernel<<<1, 32>>>(out);
}